// round 9
// baseline (speedup 1.0000x reference)
#include <cuda_runtime.h>
#include <cuda_bf16.h>
#include <math.h>

// Problem constants
#define BB   512
#define CC   128
#define TT   16
#define KK   20
#define C2   256
#define C4   512
#define CKK  2560   // K*C

// ---------------- scratch (static device globals; no allocation) ------------
__device__ float g_z   [BB * CC  * TT];
__device__ float g_y   [BB * CKK * TT];
__device__ float g_s1  [BB * C2  * TT];
__device__ float g_s2  [BB * C4  * TT];
__device__ float g_ql  [BB * CKK];
__device__ float g_mean [CKK];
__device__ float g_denom[CKK];

// ---------------- kernels ---------------------------------------------------

__global__ void zero_z_kernel(float* __restrict__ z) {
    int i = blockIdx.x * blockDim.x + threadIdx.x;
    if (i < BB * CC) z[i * TT] = 0.0f;
}

// GEMM: Y[b][m][l] = sum_c W[m][c] * IN[b][c][l]
// Single ascending-k FMA chain per output element (Eigen gebp semantics).
__global__ void gemm64_kernel(const float* __restrict__ W,
                              const float* __restrict__ inA,
                              const float* __restrict__ inB,
                              float* __restrict__ Y,
                              int M, int Cin, int L, int mode)
{
    __shared__ float As[16][68];
    __shared__ float Bs[16][68];

    const int tid = threadIdx.x;
    const int n0 = blockIdx.x * 64;
    const int m0 = blockIdx.y * 64;

    const int lk = tid >> 4;
    const int ln = (tid & 15) * 4;
    int nb[4], nl[4];
#pragma unroll
    for (int j = 0; j < 4; ++j) {
        int n = n0 + ln + j;
        nb[j] = n / L;
        nl[j] = n - nb[j] * L;
    }
    const int lm  = tid >> 2;
    const int lk4 = (tid & 3) * 4;

    const int ty = tid >> 4;
    const int tx = tid & 15;

    float acc[4][4] = {};

    for (int k0 = 0; k0 < Cin; k0 += 16) {
        float4 wv = *(const float4*)&W[(m0 + lm) * Cin + k0 + lk4];
        As[lk4 + 0][lm] = wv.x;
        As[lk4 + 1][lm] = wv.y;
        As[lk4 + 2][lm] = wv.z;
        As[lk4 + 3][lm] = wv.w;

        int c = k0 + lk;
#pragma unroll
        for (int j = 0; j < 4; ++j) {
            float v;
            if (mode == 0) {
                const float* src = (c < CC) ? inA : inB;
                int cc = c & (CC - 1);
                v = src[((nb[j] << 7) + cc) * TT + nl[j]];
            } else {
                v = inA[(nb[j] * Cin + c) * TT + nl[j]];
            }
            Bs[lk][ln + j] = v;
        }
        __syncthreads();

#pragma unroll
        for (int k = 0; k < 16; ++k) {
            float4 a = *(const float4*)&As[k][ty * 4];
            float4 b = *(const float4*)&Bs[k][tx * 4];
            float av[4] = {a.x, a.y, a.z, a.w};
            float bv[4] = {b.x, b.y, b.z, b.w};
#pragma unroll
            for (int i = 0; i < 4; ++i)
#pragma unroll
                for (int j = 0; j < 4; ++j)
                    acc[i][j] = __fmaf_rn(av[i], bv[j], acc[i][j]);
        }
        __syncthreads();
    }

#pragma unroll
    for (int j = 0; j < 4; ++j) {
        int base = (nb[j] * M + m0 + ty * 4) * TT + nl[j];
#pragma unroll
        for (int i = 0; i < 4; ++i)
            Y[base + i * TT] = acc[i][j];
    }
}

// Per-row horizontal sum (LLVM SLP shape; flip-robust within its class):
//   L>=4: one reduce at W=pow2floor(L): lanewise halving then pairwise
//         horizontal; serial scalar leftovers.
//   (L<4 handled by the caller: serial chain on the accumulator.)
__device__ __forceinline__ float row_sum4(const float* v, int L)
{
    int W = (L >= 16) ? 16 : (L >= 8) ? 8 : 4;
    float h;
    if (W == 16) {
        float l[4];
#pragma unroll
        for (int j = 0; j < 4; ++j) {
            float a = __fadd_rn(v[j],     v[8 + j]);
            float b = __fadd_rn(v[4 + j], v[12 + j]);
            l[j] = __fadd_rn(a, b);
        }
        h = __fadd_rn(__fadd_rn(l[0], l[1]), __fadd_rn(l[2], l[3]));
    } else if (W == 8) {
        float u[4];
#pragma unroll
        for (int j = 0; j < 4; ++j)
            u[j] = __fadd_rn(v[j], v[4 + j]);
        h = __fadd_rn(__fadd_rn(u[0], u[1]), __fadd_rn(u[2], u[3]));
    } else {
        h = __fadd_rn(__fadd_rn(v[0], v[1]), __fadd_rn(v[2], v[3]));
    }
    for (int t = W; t < L; ++t)
        h = __fadd_rn(h, v[t]);
    return h;
}

// Fold one row into accumulator s: L<4 serial chain on s (SLP bails);
// L>=4 s += row_sum4.
__device__ __forceinline__ float fold_row(float s, const float* v, int L)
{
    if (L < 4) {
        for (int t = 0; t < L; ++t) s = __fadd_rn(s, v[t]);
        return s;
    }
    return __fadd_rn(s, row_sum4(v, L));
}

__device__ __forceinline__ float fold_row_sq(float s, const float* v, int L, float m)
{
    float dd[16];
    for (int t = 0; t < L; ++t) {
        float d = __fsub_rn(v[t], m);
        dd[t] = __fmul_rn(d, d);
    }
    return fold_row(s, dd, L);
}

// BN stats: LLVM LoopVectorizer INTERLEAVED reduction over b (IC=2):
//   two independent accumulators — s0 takes even b, s1 takes odd b —
//   each row folded per-row (SLP shape); final fixup s = s0 + s1; mean = s/N.
// Var: identical structure over separately-rounded (y-m)^2.
__global__ void bnstats_kernel(const float* __restrict__ Y, int M, int L,
                               float* __restrict__ mean,
                               float* __restrict__ denom)
{
    int o = blockIdx.x * blockDim.x + threadIdx.x;
    if (o >= M) return;
    const float Nf = (float)(BB * L);

    // ---- mean reduce (IC=2 over b) ----
    float s0 = 0.0f, s1 = 0.0f;
    for (int b = 0; b < BB; b += 2) {
        s0 = fold_row(s0, Y + ((size_t)b       * M + o) * TT, L);
        s1 = fold_row(s1, Y + ((size_t)(b + 1) * M + o) * TT, L);
    }
    float s = __fadd_rn(s0, s1);
    float m = __fdiv_rn(s, Nf);

    // ---- var reduce (IC=2 over b, same row shape over dd) ----
    float q0 = 0.0f, q1 = 0.0f;
    for (int b = 0; b < BB; b += 2) {
        q0 = fold_row_sq(q0, Y + ((size_t)b       * M + o) * TT, L, m);
        q1 = fold_row_sq(q1, Y + ((size_t)(b + 1) * M + o) * TT, L, m);
    }
    float q = __fadd_rn(q0, q1);
    float var = __fdiv_rn(q, Nf);

    mean[o]  = m;
    denom[o] = __fsqrt_rn(__fadd_rn(var, 1e-5f));
}

// Normalize + LIF; per-op rounding (eager XLA: one executable per primitive).
__global__ void lif_kernel(const float* __restrict__ Y,
                           const float* __restrict__ mean,
                           const float* __restrict__ denom,
                           const float* __restrict__ gamma,
                           const float* __restrict__ beta,
                           int M, int L,
                           float* __restrict__ out, int last_only)
{
    int idx = blockIdx.x * blockDim.x + threadIdx.x;
    if (idx >= BB * M) return;
    int ch = idx % M;
    float mn = mean[ch], dn = denom[ch], g = gamma[ch], be = beta[ch];
    const float* yp = Y + (size_t)idx * TT;
    float u = 0.f, o = 0.f;
    for (int l = 0; l < L; ++l) {
        float t0 = __fsub_rn(yp[l], mn);
        float t1 = __fmul_rn(0.4f, t0);
        float t2 = __fdiv_rn(t1, dn);
        float t3 = __fmul_rn(t2, g);
        float yn = __fadd_rn(t3, be);
        float a  = __fmul_rn(0.25f, u);
        float bq = __fmul_rn(a, __fsub_rn(1.0f, o));
        u = __fadd_rn(bq, yn);
        o = (u > 0.2f) ? 1.0f : 0.0f;
        if (!last_only) out[(size_t)idx * TT + l] = o;
    }
    if (last_only) out[idx] = o;
}

__global__ void gather_z_kernel(const float* __restrict__ ql,
                                const int* __restrict__ ridx,
                                float* __restrict__ z, int t)
{
    int i = blockIdx.x * blockDim.x + threadIdx.x;
    if (i >= BB * CC) return;
    int b = i >> 7, c = i & 127;
    int r = ridx[t * (BB * CC) + i];
    z[i * TT + (t + 1)] = ql[b * CKK + c * KK + r];
}

__global__ void gather_sampled_kernel(const float* __restrict__ qz,
                                      const int* __restrict__ ridx,
                                      float* __restrict__ sampled)
{
    int i = blockIdx.x * blockDim.x + threadIdx.x;
    if (i >= BB * CC * TT) return;
    int t  = i & 15;
    int bc = i >> 4;
    int b  = bc >> 7, c = bc & 127;
    int r  = ridx[t * (BB * CC) + bc];
    sampled[i] = qz[((size_t)b * CKK + c * KK + r) * TT + t];
}

// ---------------- host orchestration ---------------------------------------

static float* symf(const void* sym) {
    void* p = nullptr;
    cudaGetSymbolAddress(&p, sym);
    return (float*)p;
}

extern "C" void kernel_launch(void* const* d_in, const int* in_sizes, int n_in,
                              void* d_out, int out_size)
{
    const float* x    = (const float*)d_in[0];
    const int*   ridx = (const int*)  d_in[1];
    const float* W1   = (const float*)d_in[2];
    const float* g1   = (const float*)d_in[4];
    const float* be1  = (const float*)d_in[5];
    const float* W2   = (const float*)d_in[6];
    const float* g2   = (const float*)d_in[8];
    const float* be2  = (const float*)d_in[9];
    const float* W3   = (const float*)d_in[10];
    const float* g3   = (const float*)d_in[12];
    const float* be3  = (const float*)d_in[13];

    float* out     = (float*)d_out;
    float* sampled = out;
    float* qz      = out + (size_t)BB * CC * TT;

    float* zbuf  = symf(g_z);
    float* ybuf  = symf(g_y);
    float* s1    = symf(g_s1);
    float* s2    = symf(g_s2);
    float* ql    = symf(g_ql);
    float* meanb = symf(g_mean);
    float* denb  = symf(g_denom);

    zero_z_kernel<<<(BB * CC + 255) / 256, 256>>>(zbuf);

    for (int t = 0; t < TT - 1; ++t) {
        int L = t + 1;
        gemm64_kernel<<<dim3(8 * L, C2 / 64), 256>>>(W1, x, zbuf, ybuf, C2, C2, L, 0);
        bnstats_kernel<<<(C2 + 127) / 128, 128>>>(ybuf, C2, L, meanb, denb);
        lif_kernel<<<(BB * C2) / 256, 256>>>(ybuf, meanb, denb, g1, be1, C2, L, s1, 0);

        gemm64_kernel<<<dim3(8 * L, C4 / 64), 256>>>(W2, s1, nullptr, ybuf, C4, C2, L, 1);
        bnstats_kernel<<<(C4 + 127) / 128, 128>>>(ybuf, C4, L, meanb, denb);
        lif_kernel<<<(BB * C4) / 256, 256>>>(ybuf, meanb, denb, g2, be2, C4, L, s2, 0);

        gemm64_kernel<<<dim3(8 * L, CKK / 64), 256>>>(W3, s2, nullptr, ybuf, CKK, C4, L, 1);
        bnstats_kernel<<<(CKK + 127) / 128, 128>>>(ybuf, CKK, L, meanb, denb);
        lif_kernel<<<(BB * CKK) / 256, 256>>>(ybuf, meanb, denb, g3, be3, CKK, L, ql, 1);
        gather_z_kernel<<<(BB * CC + 255) / 256, 256>>>(ql, ridx, zbuf, t);
    }

    {
        int L = TT;
        gemm64_kernel<<<dim3(8 * L, C2 / 64), 256>>>(W1, x, zbuf, ybuf, C2, C2, L, 0);
        bnstats_kernel<<<(C2 + 127) / 128, 128>>>(ybuf, C2, L, meanb, denb);
        lif_kernel<<<(BB * C2) / 256, 256>>>(ybuf, meanb, denb, g1, be1, C2, L, s1, 0);

        gemm64_kernel<<<dim3(8 * L, C4 / 64), 256>>>(W2, s1, nullptr, ybuf, C4, C2, L, 1);
        bnstats_kernel<<<(C4 + 127) / 128, 128>>>(ybuf, C4, L, meanb, denb);
        lif_kernel<<<(BB * C4) / 256, 256>>>(ybuf, meanb, denb, g2, be2, C4, L, s2, 0);

        gemm64_kernel<<<dim3(8 * L, CKK / 64), 256>>>(W3, s2, nullptr, ybuf, CKK, C4, L, 1);
        bnstats_kernel<<<(CKK + 127) / 128, 128>>>(ybuf, CKK, L, meanb, denb);
        lif_kernel<<<(BB * CKK) / 256, 256>>>(ybuf, meanb, denb, g3, be3, CKK, L, qz, 0);
    }

    gather_sampled_kernel<<<(BB * CC * TT) / 256, 256>>>(qz, ridx, sampled);
}